// round 16
// baseline (speedup 1.0000x reference)
#include <cuda_runtime.h>
#include <cuda_fp16.h>
#include <cstdint>

#define N_NODES 100000
#define FDIM    64
#define CAP     128          // slot capacity per node (mean deg = 32; overflow handled exactly)
#define OVF_CAP 65536

// ---------------- scratch (no allocs allowed) ----------------
__device__ int    g_cnt [N_NODES];          // in-degree (edges only)
__device__ float  g_dis [N_NODES];
__device__ float4 g_xs  [N_NODES];          // x * dis (pre-scaled layer-1 messages)
__device__ float4 g_xa  [N_NODES];          // layer-1 aggregate (incl. self)
__device__ uint4  g_h   [N_NODES * 8];      // hs = relu(conv1)*dis, fp16: 64 halfs = 8 uint4/node
__device__ float2 g_agg [N_NODES * 32];     // layer-2 aggregate (f32, unscaled)
__device__ int    g_slot[(size_t)N_NODES * CAP];
__device__ int    g_ovf_n;
__device__ int    g_ovf_s[OVF_CAP];
__device__ int    g_ovf_d[OVF_CAP];

__global__ void k_zero(int* cnt, int* ovf_n) {
    int i = blockIdx.x * blockDim.x + threadIdx.x;
    if (i < N_NODES) cnt[i] = 0;
    if (i == 0) *ovf_n = 0;
}

// bin edges by destination: slot[d*CAP + pos] = src. Overflow -> exact fallback list.
__global__ void k_bin(const int* __restrict__ src, const int* __restrict__ dst, int E,
                      int* __restrict__ cnt, int* __restrict__ slot,
                      int* __restrict__ ovf_n, int* __restrict__ ovf_s, int* __restrict__ ovf_d) {
    int e = blockIdx.x * blockDim.x + threadIdx.x;
    if (e < E) {
        unsigned s = (unsigned)src[e], d = (unsigned)dst[e];
        if (s < N_NODES && d < N_NODES) {
            int pos = atomicAdd(&cnt[d], 1);
            if (pos < CAP) {
                slot[(size_t)d * CAP + pos] = (int)s;
            } else {
                int o = atomicAdd(ovf_n, 1);
                if (o < OVF_CAP) { ovf_s[o] = (int)s; ovf_d[o] = (int)d; }
            }
        }
    }
}

// dis = rsqrt(cnt+1); xs = x*dis
__global__ void k_dis_xs(const float4* __restrict__ x, const int* __restrict__ cnt,
                         float* __restrict__ dis, float4* __restrict__ xs) {
    int i = blockIdx.x * blockDim.x + threadIdx.x;
    if (i < N_NODES) {
        float di = rsqrtf((float)(cnt[i] + 1));
        dis[i] = di;
        float4 xv = x[i];
        xs[i] = make_float4(xv.x * di, xv.y * di, xv.z * di, xv.w * di);
    }
}

// layer-1 aggregation: one warp per node, lanes over edges, shfl-reduce. No atomics.
// Overflow edges (normally zero) handled inline: one broadcast load of ovf_n per warp.
__global__ void k_agg1(const int* __restrict__ cnt, const int* __restrict__ slot,
                       const int* __restrict__ ovf_n, const int* __restrict__ ovf_s,
                       const int* __restrict__ ovf_d,
                       const float4* __restrict__ xs, float4* __restrict__ xa) {
    int w = (blockIdx.x * blockDim.x + threadIdx.x) >> 5;
    int lane = threadIdx.x & 31;
    if (w >= N_NODES) return;
    int n = cnt[w]; if (n > CAP) n = CAP;
    const int* sl = slot + (size_t)w * CAP;
    float ax = 0.f, ay = 0.f, az = 0.f, aw = 0.f;
    for (int e = lane; e < n; e += 32) {
        float4 v = xs[sl[e]];
        ax += v.x; ay += v.y; az += v.z; aw += v.w;
    }
    int no = *ovf_n;                           // 0 in the expected case (L1-hot broadcast)
    if (no > 0) {
        if (no > OVF_CAP) no = OVF_CAP;
        for (int i = lane; i < no; i += 32) {
            if (ovf_d[i] == w) {
                float4 v = xs[ovf_s[i]];
                ax += v.x; ay += v.y; az += v.z; aw += v.w;
            }
        }
    }
#pragma unroll
    for (int off = 16; off; off >>= 1) {
        ax += __shfl_xor_sync(0xFFFFFFFF, ax, off);
        ay += __shfl_xor_sync(0xFFFFFFFF, ay, off);
        az += __shfl_xor_sync(0xFFFFFFFF, az, off);
        aw += __shfl_xor_sync(0xFFFFFFFF, aw, off);
    }
    if (lane == 0) {
        float4 self = xs[w];
        xa[w] = make_float4(ax + self.x, ay + self.y, az + self.z, aw + self.w);
    }
}

// hs(fp16) = relu(dis*(xa @ W1) + b1) * dis
__global__ void k_dense1(const float4* __restrict__ xa,
                         const float* __restrict__ W1, const float* __restrict__ b1,
                         const float* __restrict__ dis, __half2* __restrict__ hs) {
    int idx = blockIdx.x * blockDim.x + threadIdx.x;
    if (idx < N_NODES * 32) {
        int i = idx >> 5;
        int j = (idx & 31) << 1;
        float di = dis[i];
        float4 xv = xa[i];
        float v0 = (xv.x * W1[j]   + xv.y * W1[64 + j]   + xv.z * W1[128 + j]   + xv.w * W1[192 + j])   * di + b1[j];
        float v1 = (xv.x * W1[j+1] + xv.y * W1[64 + j+1] + xv.z * W1[128 + j+1] + xv.w * W1[192 + j+1]) * di + b1[j+1];
        v0 = fmaxf(v0, 0.0f) * di;
        v1 = fmaxf(v1, 0.0f) * di;
        hs[idx] = __floats2half2_rn(v0, v1);
    }
}

__device__ __forceinline__ void acc_row(const uint4& r, float2& a0, float2& a1, float2& a2, float2& a3) {
    float2 t0 = __half22float2(*reinterpret_cast<const __half2*>(&r.x));
    float2 t1 = __half22float2(*reinterpret_cast<const __half2*>(&r.y));
    float2 t2 = __half22float2(*reinterpret_cast<const __half2*>(&r.z));
    float2 t3 = __half22float2(*reinterpret_cast<const __half2*>(&r.w));
    a0.x += t0.x; a0.y += t0.y;
    a1.x += t1.x; a1.y += t1.y;
    a2.x += t2.x; a2.y += t2.y;
    a3.x += t3.x; a3.y += t3.y;
}

// layer-2 aggregation: ONE warp per node, 4 edges per gather instruction.
// lane = (edge group g=lane>>3, chunk c=lane&7); each lane loads uint4 (16B) of
// row(edge e+g) -> one LDG.128 covers 4 edges. 2-deep unroll: 8 rows in flight.
// Cross-group combine via 16 shfl-adds; lanes g==0 add self-loop and store.
// Overflow edges (normally zero) handled inline before the combine.
__global__ void k_agg2(const int* __restrict__ cnt, const int* __restrict__ slot,
                       const int* __restrict__ ovf_n, const int* __restrict__ ovf_s,
                       const int* __restrict__ ovf_d,
                       const uint4* __restrict__ hs4, float4* __restrict__ agg4) {
    int w = (blockIdx.x * blockDim.x + threadIdx.x) >> 5;
    int lane = threadIdx.x & 31;
    if (w >= N_NODES) return;
    int g = lane >> 3;       // 0..3
    int c = lane & 7;        // 0..7
    int n = cnt[w]; if (n > CAP) n = CAP;
    const int* sl = slot + (size_t)w * CAP;

    float2 a0 = make_float2(0.f, 0.f), a1 = a0, a2 = a0, a3 = a0;
    int e = g;
    for (; e + 4 < n; e += 8) {
        int s0 = sl[e], s1 = sl[e + 4];
        uint4 r0 = hs4[(size_t)s0 * 8 + c];
        uint4 r1 = hs4[(size_t)s1 * 8 + c];
        acc_row(r0, a0, a1, a2, a3);
        acc_row(r1, a0, a1, a2, a3);
    }
    if (e < n) {
        uint4 r = hs4[(size_t)sl[e] * 8 + c];
        acc_row(r, a0, a1, a2, a3);
    }
    int no = *ovf_n;                           // 0 in the expected case (L1-hot broadcast)
    if (no > 0) {
        if (no > OVF_CAP) no = OVF_CAP;
        for (int i = g; i < no; i += 4) {
            if (ovf_d[i] == w) {
                uint4 r = hs4[(size_t)ovf_s[i] * 8 + c];
                acc_row(r, a0, a1, a2, a3);
            }
        }
    }
    // combine the 4 edge groups (lanes with equal c)
#pragma unroll
    for (int off = 8; off <= 16; off <<= 1) {
        a0.x += __shfl_xor_sync(0xFFFFFFFF, a0.x, off);
        a0.y += __shfl_xor_sync(0xFFFFFFFF, a0.y, off);
        a1.x += __shfl_xor_sync(0xFFFFFFFF, a1.x, off);
        a1.y += __shfl_xor_sync(0xFFFFFFFF, a1.y, off);
        a2.x += __shfl_xor_sync(0xFFFFFFFF, a2.x, off);
        a2.y += __shfl_xor_sync(0xFFFFFFFF, a2.y, off);
        a3.x += __shfl_xor_sync(0xFFFFFFFF, a3.x, off);
        a3.y += __shfl_xor_sync(0xFFFFFFFF, a3.y, off);
    }
    if (g == 0) {
        uint4 rs = hs4[(size_t)w * 8 + c];      // self-loop
        acc_row(rs, a0, a1, a2, a3);
        agg4[(size_t)w * 16 + 2 * c + 0] = make_float4(a0.x, a0.y, a1.x, a1.y);
        agg4[(size_t)w * 16 + 2 * c + 1] = make_float4(a2.x, a2.y, a3.x, a3.y);
    }
}

// fused: row = dis[i]*agg[i]; h2 = relu(row @ W2 + b2); out = h2 @ Wf + bf
// k-outer loop with 16 register accumulators + float4 LDS.
__global__ void k_dense2_final(const float* __restrict__ agg,
                               const float* __restrict__ dis,
                               const float* __restrict__ W2, const float* __restrict__ b2,
                               const float* __restrict__ Wf, const float* __restrict__ bf,
                               float* __restrict__ out) {
    __shared__ float sW2[64 * 64];
    __shared__ float sA [64 * 65];
    __shared__ float sWf[128];
    __shared__ float sb2[64];
    __shared__ float sbf[2];

    int t = threadIdx.x;
    int nodeBase = blockIdx.x * 64;

    for (int i = t; i < 64 * 64; i += 256) sW2[i] = W2[i];
    for (int i = t; i < 128; i += 256)     sWf[i] = Wf[i];
    if (t < 64) sb2[t] = b2[t];
    if (t < 2)  sbf[t] = bf[t];
    for (int i = t; i < 64 * 64; i += 256) {
        int node = i >> 6, k = i & 63;
        int gi = nodeBase + node;
        sA[node * 65 + k] = (gi < N_NODES) ? agg[(size_t)gi * 64 + k] * dis[gi] : 0.0f;
    }
    __syncthreads();

    int node = t >> 2;
    int part = t & 3;
    int gi = nodeBase + node;
    int f0 = part * 16;
    const float* arow = sA + node * 65;

    float acc[16];
#pragma unroll
    for (int j = 0; j < 16; ++j) acc[j] = sb2[f0 + j];

#pragma unroll 8
    for (int k = 0; k < 64; ++k) {
        float a = arow[k];
        const float4* wp = (const float4*)(sW2 + k * 64 + f0);
        float4 w0 = wp[0], w1 = wp[1], w2 = wp[2], w3 = wp[3];
        acc[0]  += a * w0.x;  acc[1]  += a * w0.y;  acc[2]  += a * w0.z;  acc[3]  += a * w0.w;
        acc[4]  += a * w1.x;  acc[5]  += a * w1.y;  acc[6]  += a * w1.z;  acc[7]  += a * w1.w;
        acc[8]  += a * w2.x;  acc[9]  += a * w2.y;  acc[10] += a * w2.z;  acc[11] += a * w2.w;
        acc[12] += a * w3.x;  acc[13] += a * w3.y;  acc[14] += a * w3.z;  acc[15] += a * w3.w;
    }

    float p0 = 0.0f, p1 = 0.0f;
#pragma unroll
    for (int j = 0; j < 16; ++j) {
        float v = fmaxf(acc[j], 0.0f);
        p0 += v * sWf[(f0 + j) * 2 + 0];
        p1 += v * sWf[(f0 + j) * 2 + 1];
    }
    p0 += __shfl_xor_sync(0xFFFFFFFF, p0, 1);
    p0 += __shfl_xor_sync(0xFFFFFFFF, p0, 2);
    p1 += __shfl_xor_sync(0xFFFFFFFF, p1, 1);
    p1 += __shfl_xor_sync(0xFFFFFFFF, p1, 2);
    if (part == 0 && gi < N_NODES) {
        out[(size_t)gi * 2 + 0] = p0 + sbf[0];
        out[(size_t)gi * 2 + 1] = p1 + sbf[1];
    }
}

extern "C" void kernel_launch(void* const* d_in, const int* in_sizes, int n_in,
                              void* d_out, int out_size) {
    const float* x  = (const float*)d_in[0];
    const int*   ei = (const int*)d_in[1];      // int32 (JAX x64 disabled)
    const float* W1 = (const float*)d_in[2];
    const float* b1 = (const float*)d_in[3];
    const float* W2 = (const float*)d_in[4];
    const float* b2 = (const float*)d_in[5];
    const float* Wf = (const float*)d_in[6];
    const float* bf = (const float*)d_in[7];
    float* out = (float*)d_out;

    int E = in_sizes[1] / 2;
    const int* src = ei;
    const int* dst = ei + E;

    int *cnt, *slot, *ovf_n, *ovf_s, *ovf_d;
    float *dis;
    float4 *xs, *xa;
    uint4 *hs;
    float2 *agg;
    cudaGetSymbolAddress((void**)&cnt,   g_cnt);
    cudaGetSymbolAddress((void**)&slot,  g_slot);
    cudaGetSymbolAddress((void**)&ovf_n, g_ovf_n);
    cudaGetSymbolAddress((void**)&ovf_s, g_ovf_s);
    cudaGetSymbolAddress((void**)&ovf_d, g_ovf_d);
    cudaGetSymbolAddress((void**)&dis,   g_dis);
    cudaGetSymbolAddress((void**)&xs,    g_xs);
    cudaGetSymbolAddress((void**)&xa,    g_xa);
    cudaGetSymbolAddress((void**)&hs,    g_h);
    cudaGetSymbolAddress((void**)&agg,   g_agg);

    const int B = 256;
    k_zero   <<<(N_NODES + B - 1) / B, B>>>(cnt, ovf_n);
    k_bin    <<<(E + B - 1) / B, B>>>(src, dst, E, cnt, slot, ovf_n, ovf_s, ovf_d);
    k_dis_xs <<<(N_NODES + B - 1) / B, B>>>((const float4*)x, cnt, dis, xs);
    k_agg1   <<<(N_NODES * 32 + B - 1) / B, B>>>(cnt, slot, ovf_n, ovf_s, ovf_d, xs, xa);
    k_dense1 <<<(N_NODES * 32 + B - 1) / B, B>>>(xa, W1, b1, dis, (__half2*)hs);
    k_agg2   <<<(N_NODES * 32 + B - 1) / B, B>>>(cnt, slot, ovf_n, ovf_s, ovf_d, hs, (float4*)agg);
    k_dense2_final<<<(N_NODES + 63) / 64, B>>>((const float*)agg, dis, W2, b2, Wf, bf, out);
}

// round 17
// speedup vs baseline: 1.0633x; 1.0633x over previous
#include <cuda_runtime.h>
#include <cuda_fp16.h>
#include <cstdint>

#define N_NODES 100000
#define FDIM    64
#define CAP     128          // slot capacity per node (mean deg = 32; overflow handled exactly)
#define OVF_CAP 65536

// ---------------- scratch (no allocs allowed) ----------------
__device__ int    g_cnt [N_NODES];          // in-degree (edges only)
__device__ float  g_dis [N_NODES];
__device__ float4 g_xs  [N_NODES];          // x * dis (pre-scaled layer-1 messages)
__device__ float4 g_xa  [N_NODES];          // layer-1 aggregate (incl. self)
__device__ uint4  g_h   [N_NODES * 8];      // hs = relu(conv1)*dis, fp16: 64 halfs = 8 uint4/node
__device__ uint4  g_agg [N_NODES * 8];      // layer-2 aggregate, fp16 (rounded once from f32 regs)
__device__ int    g_slot[(size_t)N_NODES * CAP];
__device__ int    g_ovf_n;
__device__ int    g_ovf_s[OVF_CAP];
__device__ int    g_ovf_d[OVF_CAP];

__device__ __forceinline__ void red_add_v4(float4* addr, float a, float b, float c, float d) {
    asm volatile("red.global.add.v4.f32 [%0], {%1, %2, %3, %4};"
                 :: "l"(addr), "f"(a), "f"(b), "f"(c), "f"(d) : "memory");
}

__global__ void k_zero(int* cnt, int* ovf_n) {
    int i = blockIdx.x * blockDim.x + threadIdx.x;
    if (i < N_NODES) cnt[i] = 0;
    if (i == 0) *ovf_n = 0;
}

// bin edges by destination: slot[d*CAP + pos] = src. Overflow -> exact fallback list.
__global__ void k_bin(const int* __restrict__ src, const int* __restrict__ dst, int E,
                      int* __restrict__ cnt, int* __restrict__ slot,
                      int* __restrict__ ovf_n, int* __restrict__ ovf_s, int* __restrict__ ovf_d) {
    int e = blockIdx.x * blockDim.x + threadIdx.x;
    if (e < E) {
        unsigned s = (unsigned)src[e], d = (unsigned)dst[e];
        if (s < N_NODES && d < N_NODES) {
            int pos = atomicAdd(&cnt[d], 1);
            if (pos < CAP) {
                slot[(size_t)d * CAP + pos] = (int)s;
            } else {
                int o = atomicAdd(ovf_n, 1);
                if (o < OVF_CAP) { ovf_s[o] = (int)s; ovf_d[o] = (int)d; }
            }
        }
    }
}

// dis = rsqrt(cnt+1); xs = x*dis
__global__ void k_dis_xs(const float4* __restrict__ x, const int* __restrict__ cnt,
                         float* __restrict__ dis, float4* __restrict__ xs) {
    int i = blockIdx.x * blockDim.x + threadIdx.x;
    if (i < N_NODES) {
        float di = rsqrtf((float)(cnt[i] + 1));
        dis[i] = di;
        float4 xv = x[i];
        xs[i] = make_float4(xv.x * di, xv.y * di, xv.z * di, xv.w * di);
    }
}

// layer-1 aggregation: one warp per node, lanes over edges, shfl-reduce. No atomics.
__global__ void k_agg1(const int* __restrict__ cnt, const int* __restrict__ slot,
                       const float4* __restrict__ xs, float4* __restrict__ xa) {
    int w = (blockIdx.x * blockDim.x + threadIdx.x) >> 5;
    int lane = threadIdx.x & 31;
    if (w >= N_NODES) return;
    int n = cnt[w]; if (n > CAP) n = CAP;
    const int* sl = slot + (size_t)w * CAP;
    float ax = 0.f, ay = 0.f, az = 0.f, aw = 0.f;
    for (int e = lane; e < n; e += 32) {
        float4 v = xs[sl[e]];
        ax += v.x; ay += v.y; az += v.z; aw += v.w;
    }
#pragma unroll
    for (int off = 16; off; off >>= 1) {
        ax += __shfl_xor_sync(0xFFFFFFFF, ax, off);
        ay += __shfl_xor_sync(0xFFFFFFFF, ay, off);
        az += __shfl_xor_sync(0xFFFFFFFF, az, off);
        aw += __shfl_xor_sync(0xFFFFFFFF, aw, off);
    }
    if (lane == 0) {
        float4 self = xs[w];
        xa[w] = make_float4(ax + self.x, ay + self.y, az + self.z, aw + self.w);
    }
}

// overflow edges, layer 1 (exact fallback; normally empty). Grid-stride.
__global__ void k_ovf1(const int* __restrict__ ovf_n, const int* __restrict__ ovf_s,
                       const int* __restrict__ ovf_d,
                       const float4* __restrict__ xs, float4* __restrict__ xa) {
    int n = *ovf_n; if (n > OVF_CAP) n = OVF_CAP;
    for (int i = blockIdx.x * blockDim.x + threadIdx.x; i < n; i += gridDim.x * blockDim.x) {
        float4 v = xs[ovf_s[i]];
        red_add_v4(xa + ovf_d[i], v.x, v.y, v.z, v.w);
    }
}

// hs(fp16) = relu(dis*(xa @ W1) + b1) * dis
__global__ void k_dense1(const float4* __restrict__ xa,
                         const float* __restrict__ W1, const float* __restrict__ b1,
                         const float* __restrict__ dis, __half2* __restrict__ hs) {
    int idx = blockIdx.x * blockDim.x + threadIdx.x;
    if (idx < N_NODES * 32) {
        int i = idx >> 5;
        int j = (idx & 31) << 1;
        float di = dis[i];
        float4 xv = xa[i];
        float v0 = (xv.x * W1[j]   + xv.y * W1[64 + j]   + xv.z * W1[128 + j]   + xv.w * W1[192 + j])   * di + b1[j];
        float v1 = (xv.x * W1[j+1] + xv.y * W1[64 + j+1] + xv.z * W1[128 + j+1] + xv.w * W1[192 + j+1]) * di + b1[j+1];
        v0 = fmaxf(v0, 0.0f) * di;
        v1 = fmaxf(v1, 0.0f) * di;
        hs[idx] = __floats2half2_rn(v0, v1);
    }
}

__device__ __forceinline__ void acc_row(const uint4& r, float2& a0, float2& a1, float2& a2, float2& a3) {
    float2 t0 = __half22float2(*reinterpret_cast<const __half2*>(&r.x));
    float2 t1 = __half22float2(*reinterpret_cast<const __half2*>(&r.y));
    float2 t2 = __half22float2(*reinterpret_cast<const __half2*>(&r.z));
    float2 t3 = __half22float2(*reinterpret_cast<const __half2*>(&r.w));
    a0.x += t0.x; a0.y += t0.y;
    a1.x += t1.x; a1.y += t1.y;
    a2.x += t2.x; a2.y += t2.y;
    a3.x += t3.x; a3.y += t3.y;
}

// layer-2 aggregation: ONE warp per node, 4 edges per gather instruction.
// lane = (edge group g=lane>>3, chunk c=lane&7); each lane loads uint4 (16B) of
// row(edge e+g) -> one LDG.128 covers 4 edges. 2-deep unroll: 8 rows in flight.
// Cross-group combine via 16 shfl-adds; lanes g==0 add self-loop and store fp16.
__global__ void k_agg2(const int* __restrict__ cnt, const int* __restrict__ slot,
                       const uint4* __restrict__ hs4, uint4* __restrict__ aggh) {
    int w = (blockIdx.x * blockDim.x + threadIdx.x) >> 5;
    int lane = threadIdx.x & 31;
    if (w >= N_NODES) return;
    int g = lane >> 3;       // 0..3
    int c = lane & 7;        // 0..7
    int n = cnt[w]; if (n > CAP) n = CAP;
    const int* sl = slot + (size_t)w * CAP;

    float2 a0 = make_float2(0.f, 0.f), a1 = a0, a2 = a0, a3 = a0;
    int e = g;
    for (; e + 4 < n; e += 8) {
        int s0 = sl[e], s1 = sl[e + 4];
        uint4 r0 = hs4[(size_t)s0 * 8 + c];
        uint4 r1 = hs4[(size_t)s1 * 8 + c];
        acc_row(r0, a0, a1, a2, a3);
        acc_row(r1, a0, a1, a2, a3);
    }
    if (e < n) {
        uint4 r = hs4[(size_t)sl[e] * 8 + c];
        acc_row(r, a0, a1, a2, a3);
    }
    // combine the 4 edge groups (lanes with equal c)
#pragma unroll
    for (int off = 8; off <= 16; off <<= 1) {
        a0.x += __shfl_xor_sync(0xFFFFFFFF, a0.x, off);
        a0.y += __shfl_xor_sync(0xFFFFFFFF, a0.y, off);
        a1.x += __shfl_xor_sync(0xFFFFFFFF, a1.x, off);
        a1.y += __shfl_xor_sync(0xFFFFFFFF, a1.y, off);
        a2.x += __shfl_xor_sync(0xFFFFFFFF, a2.x, off);
        a2.y += __shfl_xor_sync(0xFFFFFFFF, a2.y, off);
        a3.x += __shfl_xor_sync(0xFFFFFFFF, a3.x, off);
        a3.y += __shfl_xor_sync(0xFFFFFFFF, a3.y, off);
    }
    if (g == 0) {
        uint4 rs = hs4[(size_t)w * 8 + c];      // self-loop
        acc_row(rs, a0, a1, a2, a3);
        __half2 h0 = __floats2half2_rn(a0.x, a0.y);
        __half2 h1 = __floats2half2_rn(a1.x, a1.y);
        __half2 h2 = __floats2half2_rn(a2.x, a2.y);
        __half2 h3 = __floats2half2_rn(a3.x, a3.y);
        uint4 o;
        o.x = *reinterpret_cast<uint32_t*>(&h0);
        o.y = *reinterpret_cast<uint32_t*>(&h1);
        o.z = *reinterpret_cast<uint32_t*>(&h2);
        o.w = *reinterpret_cast<uint32_t*>(&h3);
        aggh[(size_t)w * 8 + c] = o;
    }
}

// overflow edges, layer 2 (exact fallback; normally empty). Grid-stride, half2 atomics.
__global__ void k_ovf2(const int* __restrict__ ovf_n, const int* __restrict__ ovf_s,
                       const int* __restrict__ ovf_d,
                       const __half2* __restrict__ hs, __half2* __restrict__ aggh2) {
    int n = *ovf_n; if (n > OVF_CAP) n = OVF_CAP;
    for (int i = blockIdx.x * blockDim.x + threadIdx.x; i < n; i += gridDim.x * blockDim.x) {
        int s = ovf_s[i], d = ovf_d[i];
        for (int c = 0; c < 32; ++c)
            atomicAdd(&aggh2[(size_t)d * 32 + c], hs[(size_t)s * 32 + c]);
    }
}

// fused: row = dis[i]*agg[i]; h2 = relu(row @ W2 + b2); out = h2 @ Wf + bf
// fp16 agg read (uint4 = 8 halfs per load); k-outer loop, 16 register accumulators.
__global__ void k_dense2_final(const uint4* __restrict__ aggh,
                               const float* __restrict__ dis,
                               const float* __restrict__ W2, const float* __restrict__ b2,
                               const float* __restrict__ Wf, const float* __restrict__ bf,
                               float* __restrict__ out) {
    __shared__ float sW2[64 * 64];
    __shared__ float sA [64 * 65];
    __shared__ float sWf[128];
    __shared__ float sb2[64];
    __shared__ float sbf[2];

    int t = threadIdx.x;
    int nodeBase = blockIdx.x * 64;

    for (int i = t; i < 64 * 64; i += 256) sW2[i] = W2[i];
    for (int i = t; i < 128; i += 256)     sWf[i] = Wf[i];
    if (t < 64) sb2[t] = b2[t];
    if (t < 2)  sbf[t] = bf[t];
    // fill sA: 64 nodes x 8 chunks; each iteration loads one uint4 (8 halfs)
    for (int i = t; i < 64 * 8; i += 256) {
        int node = i >> 3, c = i & 7;
        int gi = nodeBase + node;
        float* dstp = sA + node * 65 + c * 8;
        if (gi < N_NODES) {
            float di = dis[gi];
            uint4 r = aggh[(size_t)gi * 8 + c];
            float2 t0 = __half22float2(*reinterpret_cast<const __half2*>(&r.x));
            float2 t1 = __half22float2(*reinterpret_cast<const __half2*>(&r.y));
            float2 t2 = __half22float2(*reinterpret_cast<const __half2*>(&r.z));
            float2 t3 = __half22float2(*reinterpret_cast<const __half2*>(&r.w));
            dstp[0] = t0.x * di; dstp[1] = t0.y * di;
            dstp[2] = t1.x * di; dstp[3] = t1.y * di;
            dstp[4] = t2.x * di; dstp[5] = t2.y * di;
            dstp[6] = t3.x * di; dstp[7] = t3.y * di;
        } else {
            for (int m = 0; m < 8; ++m) dstp[m] = 0.0f;
        }
    }
    __syncthreads();

    int node = t >> 2;
    int part = t & 3;
    int gi = nodeBase + node;
    int f0 = part * 16;
    const float* arow = sA + node * 65;

    float acc[16];
#pragma unroll
    for (int j = 0; j < 16; ++j) acc[j] = sb2[f0 + j];

#pragma unroll 8
    for (int k = 0; k < 64; ++k) {
        float a = arow[k];
        const float4* wp = (const float4*)(sW2 + k * 64 + f0);
        float4 w0 = wp[0], w1 = wp[1], w2 = wp[2], w3 = wp[3];
        acc[0]  += a * w0.x;  acc[1]  += a * w0.y;  acc[2]  += a * w0.z;  acc[3]  += a * w0.w;
        acc[4]  += a * w1.x;  acc[5]  += a * w1.y;  acc[6]  += a * w1.z;  acc[7]  += a * w1.w;
        acc[8]  += a * w2.x;  acc[9]  += a * w2.y;  acc[10] += a * w2.z;  acc[11] += a * w2.w;
        acc[12] += a * w3.x;  acc[13] += a * w3.y;  acc[14] += a * w3.z;  acc[15] += a * w3.w;
    }

    float p0 = 0.0f, p1 = 0.0f;
#pragma unroll
    for (int j = 0; j < 16; ++j) {
        float v = fmaxf(acc[j], 0.0f);
        p0 += v * sWf[(f0 + j) * 2 + 0];
        p1 += v * sWf[(f0 + j) * 2 + 1];
    }
    p0 += __shfl_xor_sync(0xFFFFFFFF, p0, 1);
    p0 += __shfl_xor_sync(0xFFFFFFFF, p0, 2);
    p1 += __shfl_xor_sync(0xFFFFFFFF, p1, 1);
    p1 += __shfl_xor_sync(0xFFFFFFFF, p1, 2);
    if (part == 0 && gi < N_NODES) {
        out[(size_t)gi * 2 + 0] = p0 + sbf[0];
        out[(size_t)gi * 2 + 1] = p1 + sbf[1];
    }
}

extern "C" void kernel_launch(void* const* d_in, const int* in_sizes, int n_in,
                              void* d_out, int out_size) {
    const float* x  = (const float*)d_in[0];
    const int*   ei = (const int*)d_in[1];      // int32 (JAX x64 disabled)
    const float* W1 = (const float*)d_in[2];
    const float* b1 = (const float*)d_in[3];
    const float* W2 = (const float*)d_in[4];
    const float* b2 = (const float*)d_in[5];
    const float* Wf = (const float*)d_in[6];
    const float* bf = (const float*)d_in[7];
    float* out = (float*)d_out;

    int E = in_sizes[1] / 2;
    const int* src = ei;
    const int* dst = ei + E;

    int *cnt, *slot, *ovf_n, *ovf_s, *ovf_d;
    float *dis;
    float4 *xs, *xa;
    uint4 *hs, *agg;
    cudaGetSymbolAddress((void**)&cnt,   g_cnt);
    cudaGetSymbolAddress((void**)&slot,  g_slot);
    cudaGetSymbolAddress((void**)&ovf_n, g_ovf_n);
    cudaGetSymbolAddress((void**)&ovf_s, g_ovf_s);
    cudaGetSymbolAddress((void**)&ovf_d, g_ovf_d);
    cudaGetSymbolAddress((void**)&dis,   g_dis);
    cudaGetSymbolAddress((void**)&xs,    g_xs);
    cudaGetSymbolAddress((void**)&xa,    g_xa);
    cudaGetSymbolAddress((void**)&hs,    g_h);
    cudaGetSymbolAddress((void**)&agg,   g_agg);

    const int B = 256;
    k_zero   <<<(N_NODES + B - 1) / B, B>>>(cnt, ovf_n);
    k_bin    <<<(E + B - 1) / B, B>>>(src, dst, E, cnt, slot, ovf_n, ovf_s, ovf_d);
    k_dis_xs <<<(N_NODES + B - 1) / B, B>>>((const float4*)x, cnt, dis, xs);
    k_agg1   <<<(N_NODES * 32 + B - 1) / B, B>>>(cnt, slot, xs, xa);
    k_ovf1   <<<64, B>>>(ovf_n, ovf_s, ovf_d, xs, xa);
    k_dense1 <<<(N_NODES * 32 + B - 1) / B, B>>>(xa, W1, b1, dis, (__half2*)hs);
    k_agg2   <<<(N_NODES * 32 + B - 1) / B, B>>>(cnt, slot, hs, agg);
    k_ovf2   <<<64, B>>>(ovf_n, ovf_s, ovf_d, (const __half2*)hs, (__half2*)agg);
    k_dense2_final<<<(N_NODES + 63) / 64, B>>>(agg, dis, W2, b2, Wf, bf, out);
}